// round 5
// baseline (speedup 1.0000x reference)
#include <cuda_runtime.h>

// ---------------------------------------------------------------------------
// MaskedBalancedBCELoss — 3-kernel pipeline.
//  K1 (one 157 MB streaming read): counts pos/valid in registers; 16-bin u8
//     histogram of p over CANDIDATES only (negatives with p>=0.5); compacts
//     candidate preds to scratch front (ballot-aggregated) and positive preds
//     to scratch back (sparse shared-atomic).
//  K2: derives threshold bin T1 (in 16..31) from the histogram; two
//     non-divergent loops over scratch: negative candidates (exact loss for
//     bins > T1; 64-sub-bin count/sum hist inside T1) and positives (loss
//     sum). If T1 would fall below bin 16 (k > #candidates) -> full re-read
//     with a 1024-fine-bin histogram (same 1/2048 resolution). If scratch
//     doesn't fit -> full re-read. Always correct.
//  K3: resolves the crossing sub-bin (mean interpolation), writes scalar,
//     resets all globals (graph-replay safe).
// ---------------------------------------------------------------------------

#define NB1 16             // bins 16..31 of (int)(p*32)
#define NB2 64
#define NFB 1024           // fine bins over [0,0.5) for the cold fallback
#define BLK 256
#define GRID_CAP 888
#define SCR_SZ (16u << 20) // 16M floats = 64 MB

__device__ float        g_scr[SCR_SZ];
__device__ unsigned int g_cnt_neg[GRID_CAP];
__device__ unsigned int g_cnt_pos[GRID_CAP];
__device__ unsigned int g_h1[NB1];
__device__ unsigned int g_h2c[NB2];
__device__ float        g_h2s[NB2];
__device__ unsigned int g_fc[NFB];
__device__ float        g_fs[NFB];
__device__ unsigned int g_pos_cnt;
__device__ unsigned int g_neg_cnt;
__device__ double       g_pos_sum;
__device__ double       g_above_sum;

// Cephes-style natural log, pure FMA/ALU (no MUFU). ~1-2 ulp on normals.
__device__ __forceinline__ float fast_log(float x) {
    int   i  = __float_as_int(x);
    int   e  = ((i >> 23) & 0xFF) - 127;
    float m  = __int_as_float((i & 0x007FFFFF) | 0x3F800000);
    if (m > 1.41421356f) { m *= 0.5f; e += 1; }
    float t  = m - 1.0f;
    float z  = t * t;
    float P  = 7.0376836292e-2f;
    P = P * t - 1.1514610310e-1f;
    P = P * t + 1.1676998740e-1f;
    P = P * t - 1.2420140846e-1f;
    P = P * t + 1.4249322787e-1f;
    P = P * t - 1.6668057665e-1f;
    P = P * t + 2.0000714765e-1f;
    P = P * t - 2.4999993993e-1f;
    P = P * t + 3.3333331174e-1f;
    float fe = (float)e;
    float y  = t * z * P;
    y += fe * -2.12194440e-4f;
    y -= 0.5f * z;
    float r  = t + y;
    r += fe * 0.693359375f;
    return r;
}
__device__ __forceinline__ float pos_loss_f(float p) { return fminf(-fast_log(p), 100.0f); }
__device__ __forceinline__ float neg_loss_f(float p) { return fminf(-fast_log(1.0f - p), 100.0f); }

// Shared logic: threshold bin from {16-bin hist, neg_total, pos}.
// Returns: 1000 if k==0; -1 if threshold falls below bin 16 (cold); else T1 in [16,31].
__device__ __forceinline__ int find_T1(const unsigned* h1, unsigned pos,
                                       long long negtot, long long& k_out) {
    long long k3p = 3LL * (long long)pos;
    long long k = (pos == 0u) ? 0LL : (negtot < k3p ? negtot : k3p);
    k_out = k;
    if (k == 0) return 1000;
    long long c = 0;
    for (int i = NB1 - 1; i >= 0; i--) {
        c += (long long)h1[i];
        if (c >= k) return i + 16;
    }
    return -1;
}

// ---------------------------------------------------------------------------
// K1
// ---------------------------------------------------------------------------
__global__ void __launch_bounds__(BLK) k1_scan(
    const float4* __restrict__ pred4, const float4* __restrict__ gt4,
    const float4* __restrict__ mask4,
    const float* __restrict__ pred, const float* __restrict__ gt,
    const float* __restrict__ mask, int n, int cap, int use_scr)
{
    __shared__ unsigned int sh[4 * BLK];     // u8-packed 16-bin candidate hist
    __shared__ unsigned int s_binsum[NB1];
    __shared__ unsigned int s_cntn, s_cntp;
    __shared__ unsigned int w_pc[BLK / 32], w_vc[BLK / 32];

    const int tid  = threadIdx.x;
    const int lane = tid & 31;
    const unsigned lt = (1u << lane) - 1u;

#pragma unroll
    for (int w = 0; w < 4; w++) sh[w * BLK + tid] = 0u;
    if (tid < NB1) s_binsum[tid] = 0u;
    if (tid == 0) { s_cntn = 0u; s_cntp = 0u; }
    __syncthreads();

    unsigned int posc = 0, valc = 0;
    const int n4   = n >> 2;
    const int step = gridDim.x * BLK;
    const long long rb = (long long)blockIdx.x * (long long)cap;

    // classify one element; candidates (neg, p>=0.5) histogrammed; positives
    // stored to scratch back immediately (rare path).
    auto procE = [&](float p, float g, float mm, bool in) -> bool {
        bool valid = in && (mm > 0.5f);
        bool ispos = valid && (g > 0.5f);
        valc += valid ? 1u : 0u;
        posc += ispos ? 1u : 0u;
        if (ispos) {
            if (use_scr) {
                unsigned o = atomicAdd(&s_cntp, 1u);
                g_scr[rb + cap - 1 - (long long)o] = p;
            }
            return false;
        }
        bool cand = valid && (p >= 0.5f);
        if (cand) {
            int idx = min((int)(p * 32.0f), 31) - 16;   // 0..15
            sh[(idx >> 2) * BLK + tid] += 1u << ((idx & 3) << 3);
        }
        return cand;
    };

    auto flushHist = [&]() {   // all-threads, conflict-free staggered
        const int b     = tid & 15;
        const int chunk = tid >> 4;
        const int w     = (b >> 2) * BLK;
        const int shft  = (b & 3) << 3;
        unsigned s = 0;
#pragma unroll
        for (int jj = 0; jj < 16; jj++) {
            int j = chunk * 16 + ((jj + b) & 15);
            s += (sh[w + j] >> shft) & 0xFFu;
        }
        if (s) atomicAdd(&s_binsum[b], s);
    };

    int ibase = blockIdx.x * BLK;
    int fl = 0;
    while (ibase + step + BLK <= n4) {
        int i0 = ibase + tid, i1 = i0 + step;
        float4 pa = __ldcs(&pred4[i0]), ga = __ldcs(&gt4[i0]), ma = __ldcs(&mask4[i0]);
        float4 pb = __ldcs(&pred4[i1]), gb = __ldcs(&gt4[i1]), mb = __ldcs(&mask4[i1]);
        bool c0 = procE(pa.x, ga.x, ma.x, true);
        bool c1 = procE(pa.y, ga.y, ma.y, true);
        bool c2 = procE(pa.z, ga.z, ma.z, true);
        bool c3 = procE(pa.w, ga.w, ma.w, true);
        bool c4 = procE(pb.x, gb.x, mb.x, true);
        bool c5 = procE(pb.y, gb.y, mb.y, true);
        bool c6 = procE(pb.z, gb.z, mb.z, true);
        bool c7 = procE(pb.w, gb.w, mb.w, true);
        if (use_scr) {
            unsigned m0 = __ballot_sync(0xffffffffu, c0);
            unsigned m1 = __ballot_sync(0xffffffffu, c1);
            unsigned m2 = __ballot_sync(0xffffffffu, c2);
            unsigned m3 = __ballot_sync(0xffffffffu, c3);
            unsigned m4 = __ballot_sync(0xffffffffu, c4);
            unsigned m5 = __ballot_sync(0xffffffffu, c5);
            unsigned m6 = __ballot_sync(0xffffffffu, c6);
            unsigned m7 = __ballot_sync(0xffffffffu, c7);
            unsigned tot = __popc(m0) + __popc(m1) + __popc(m2) + __popc(m3)
                         + __popc(m4) + __popc(m5) + __popc(m6) + __popc(m7);
            unsigned base = 0;
            if (lane == 0 && tot) base = atomicAdd(&s_cntn, tot);
            base = __shfl_sync(0xffffffffu, base, 0);
            unsigned s = base;
            if (c0) g_scr[rb + s + __popc(m0 & lt)] = pa.x; s += __popc(m0);
            if (c1) g_scr[rb + s + __popc(m1 & lt)] = pa.y; s += __popc(m1);
            if (c2) g_scr[rb + s + __popc(m2 & lt)] = pa.z; s += __popc(m2);
            if (c3) g_scr[rb + s + __popc(m3 & lt)] = pa.w; s += __popc(m3);
            if (c4) g_scr[rb + s + __popc(m4 & lt)] = pb.x; s += __popc(m4);
            if (c5) g_scr[rb + s + __popc(m5 & lt)] = pb.y; s += __popc(m5);
            if (c6) g_scr[rb + s + __popc(m6 & lt)] = pb.z; s += __popc(m6);
            if (c7) g_scr[rb + s + __popc(m7 & lt)] = pb.w;
        }
        ibase += 2 * step;
        if (++fl >= 19) {   // u8 overflow guard: 19*8 + 12 < 255 (uniform path)
            __syncthreads(); flushHist(); __syncthreads();
#pragma unroll
            for (int w = 0; w < 4; w++) sh[w * BLK + tid] = 0u;
            __syncthreads();
            fl = 0;
        }
    }
    // remainder (block-uniform trips, predicated loads; ballot stays legal)
    for (; ibase < n4; ibase += step) {
        int i = ibase + tid;
        bool in = i < n4;
        float4 pa = in ? __ldcs(&pred4[i]) : make_float4(0.f, 0.f, 0.f, 0.f);
        float4 ga = in ? __ldcs(&gt4[i])   : make_float4(1.f, 1.f, 1.f, 1.f);
        float4 ma = in ? __ldcs(&mask4[i]) : make_float4(0.f, 0.f, 0.f, 0.f);
        bool c0 = procE(pa.x, ga.x, ma.x, in);
        bool c1 = procE(pa.y, ga.y, ma.y, in);
        bool c2 = procE(pa.z, ga.z, ma.z, in);
        bool c3 = procE(pa.w, ga.w, ma.w, in);
        if (use_scr) {
            unsigned m0 = __ballot_sync(0xffffffffu, c0);
            unsigned m1 = __ballot_sync(0xffffffffu, c1);
            unsigned m2 = __ballot_sync(0xffffffffu, c2);
            unsigned m3 = __ballot_sync(0xffffffffu, c3);
            unsigned tot = __popc(m0) + __popc(m1) + __popc(m2) + __popc(m3);
            unsigned base = 0;
            if (lane == 0 && tot) base = atomicAdd(&s_cntn, tot);
            base = __shfl_sync(0xffffffffu, base, 0);
            unsigned s = base;
            if (c0) g_scr[rb + s + __popc(m0 & lt)] = pa.x; s += __popc(m0);
            if (c1) g_scr[rb + s + __popc(m1 & lt)] = pa.y; s += __popc(m1);
            if (c2) g_scr[rb + s + __popc(m2 & lt)] = pa.z; s += __popc(m2);
            if (c3) g_scr[rb + s + __popc(m3 & lt)] = pa.w;
        }
    }
    __syncthreads();
    flushHist();
    __syncthreads();

    // scalar tail (n % 4), block 0 only; direct shared atomics
    if (blockIdx.x == 0) {
        for (int i = (n4 << 2) + tid; i < n; i += BLK) {
            float p = pred[i], g = gt[i], mm = mask[i];
            bool valid = mm > 0.5f;
            bool ispos = valid && (g > 0.5f);
            if (valid) valc++;
            if (ispos) {
                posc++;
                if (use_scr) {
                    unsigned o = atomicAdd(&s_cntp, 1u);
                    g_scr[rb + cap - 1 - (long long)o] = p;
                }
            } else if (valid && p >= 0.5f) {
                int idx = min((int)(p * 32.0f), 31) - 16;
                atomicAdd(&s_binsum[idx], 1u);
                if (use_scr) {
                    unsigned o = atomicAdd(&s_cntn, 1u);
                    g_scr[rb + o] = p;
                }
            }
        }
    }

#pragma unroll
    for (int o = 16; o > 0; o >>= 1) {
        posc += __shfl_down_sync(0xffffffffu, posc, o);
        valc += __shfl_down_sync(0xffffffffu, valc, o);
    }
    if (lane == 0) { w_pc[tid >> 5] = posc; w_vc[tid >> 5] = valc; }
    __syncthreads();

    if (tid < NB1 && s_binsum[tid]) atomicAdd(&g_h1[tid], s_binsum[tid]);
    if (tid == 0) {
        unsigned pc = 0, vc = 0;
#pragma unroll
        for (int w = 0; w < BLK / 32; w++) { pc += w_pc[w]; vc += w_vc[w]; }
        if (pc) atomicAdd(&g_pos_cnt, pc);
        if (vc - pc) atomicAdd(&g_neg_cnt, vc - pc);
        g_cnt_neg[blockIdx.x] = s_cntn;
        g_cnt_pos[blockIdx.x] = s_cntp;
    }
}

// ---------------------------------------------------------------------------
// K2
// ---------------------------------------------------------------------------
__global__ void __launch_bounds__(BLK) k2_refine(
    const float4* __restrict__ pred4, const float4* __restrict__ gt4,
    const float4* __restrict__ mask4,
    const float* __restrict__ pred, const float* __restrict__ gt,
    const float* __restrict__ mask, int n, int cap, int use_scr)
{
    __shared__ unsigned int s_h1[NB1];
    __shared__ int          s_T1;
    __shared__ unsigned int s_c2[NB2];
    __shared__ float        s_s2[NB2];
    __shared__ unsigned int s_fc[NFB];
    __shared__ float        s_fs[NFB];
    __shared__ float        w_as[BLK / 32], w_ps[BLK / 32];

    const int tid = threadIdx.x;
    if (tid < NB1) s_h1[tid] = g_h1[tid];
    if (tid < NB2) { s_c2[tid] = 0u; s_s2[tid] = 0.0f; }
    for (int i = tid; i < NFB; i += BLK) { s_fc[i] = 0u; s_fs[i] = 0.0f; }
    __syncthreads();

    if (tid == 0) {
        long long k;
        s_T1 = find_T1(s_h1, g_pos_cnt, (long long)g_neg_cnt, k);
    }
    __syncthreads();
    const int T1 = s_T1;

    float asum = 0.0f, psum = 0.0f;
    bool wrote_fine = false;

    if (use_scr && T1 >= 16 && T1 < 32) {
        // ---- fast path: negatives loop (no divergence with positives) ----
        const long long rb  = (long long)blockIdx.x * (long long)cap;
        const unsigned  cnt = g_cnt_neg[blockIdx.x];
        const float4*   s4  = (const float4*)&g_scr[rb];
        const unsigned  c4  = cnt >> 2;
        auto hneg = [&](float p) {
            int b = min((int)(p * 32.0f), 31);
            if (b > T1) {
                asum += neg_loss_f(p);
            } else if (b == T1) {
                int b2 = (int)(p * 2048.0f) - T1 * 64;
                b2 = max(0, min(b2, NB2 - 1));
                atomicAdd(&s_c2[b2], 1u);
                atomicAdd(&s_s2[b2], neg_loss_f(p));
            }
        };
        for (unsigned j = tid; j < c4; j += BLK) {
            float4 v = s4[j];
            hneg(v.x); hneg(v.y); hneg(v.z); hneg(v.w);
        }
        for (unsigned j = (c4 << 2) + tid; j < cnt; j += BLK) hneg(g_scr[rb + j]);
        // ---- positives loop ----
        const unsigned pcnt = g_cnt_pos[blockIdx.x];
        const long long pb  = rb + (long long)cap - (long long)pcnt;
        for (unsigned j = tid; j < pcnt; j += BLK) psum += pos_loss_f(g_scr[pb + j]);
    } else if (use_scr && T1 == 1000) {
        // k == 0: only positive losses needed
        const long long rb   = (long long)blockIdx.x * (long long)cap;
        const unsigned  pcnt = g_cnt_pos[blockIdx.x];
        const long long pb   = rb + (long long)cap - (long long)pcnt;
        for (unsigned j = tid; j < pcnt; j += BLK) psum += pos_loss_f(g_scr[pb + j]);
    } else {
        // ---- cold path: full re-read ----
        const bool fine = (T1 < 16);   // threshold below candidate range
        wrote_fine = fine;
        const int n4 = n >> 2;
        const int stp = gridDim.x * BLK;
        auto hfull = [&](float p, float g, float mm) {
            if (mm > 0.5f) {
                if (g > 0.5f) { psum += pos_loss_f(p); return; }
                if (T1 == 1000) return;
                if (fine) {
                    if (p >= 0.5f) { asum += neg_loss_f(p); }
                    else {
                        int fb = max(0, min((int)(p * 2048.0f), NFB - 1));
                        atomicAdd(&s_fc[fb], 1u);
                        atomicAdd(&s_fs[fb], neg_loss_f(p));
                    }
                } else {
                    int b = min((int)(p * 32.0f), 31);
                    if (b > T1) asum += neg_loss_f(p);
                    else if (b == T1) {
                        int b2 = (int)(p * 2048.0f) - T1 * 64;
                        b2 = max(0, min(b2, NB2 - 1));
                        atomicAdd(&s_c2[b2], 1u);
                        atomicAdd(&s_s2[b2], neg_loss_f(p));
                    }
                }
            }
        };
        for (int ib = blockIdx.x * BLK; ib < n4; ib += stp) {
            int i = ib + tid;
            if (i < n4) {
                float4 p = pred4[i], g = gt4[i], m = mask4[i];
                hfull(p.x, g.x, m.x); hfull(p.y, g.y, m.y);
                hfull(p.z, g.z, m.z); hfull(p.w, g.w, m.w);
            }
        }
        if (blockIdx.x == 0) {
            for (int i = (n4 << 2) + tid; i < n; i += BLK)
                hfull(pred[i], gt[i], mask[i]);
        }
    }

#pragma unroll
    for (int o = 16; o > 0; o >>= 1) {
        asum += __shfl_down_sync(0xffffffffu, asum, o);
        psum += __shfl_down_sync(0xffffffffu, psum, o);
    }
    if ((tid & 31) == 0) { w_as[tid >> 5] = asum; w_ps[tid >> 5] = psum; }
    __syncthreads();

    if (tid < NB2 && s_c2[tid]) {
        atomicAdd(&g_h2c[tid], s_c2[tid]);
        atomicAdd(&g_h2s[tid], s_s2[tid]);
    }
    if (wrote_fine) {
        for (int i = tid; i < NFB; i += BLK) {
            if (s_fc[i]) { atomicAdd(&g_fc[i], s_fc[i]); atomicAdd(&g_fs[i], s_fs[i]); }
        }
    }
    if (tid == 0) {
        float as = 0.0f, ps = 0.0f;
#pragma unroll
        for (int w = 0; w < BLK / 32; w++) { as += w_as[w]; ps += w_ps[w]; }
        atomicAdd(&g_above_sum, (double)as);
        atomicAdd(&g_pos_sum, (double)ps);
    }
}

// ---------------------------------------------------------------------------
// K3: finalize + reset globals
// ---------------------------------------------------------------------------
__global__ void k3_finalize(float* __restrict__ out)
{
    const int tid = threadIdx.x;
    if (tid == 0) {
        unsigned pos = g_pos_cnt;
        long long k;
        unsigned h1[NB1];
        for (int i = 0; i < NB1; i++) h1[i] = g_h1[i];
        int T1 = find_T1(h1, pos, (long long)g_neg_cnt, k);

        double nsum = 0.0;
        if (k > 0) {
            if (T1 >= 16) {
                long long cAbove1 = 0;
                for (int i = T1 + 1 - 16; i < NB1; i++) cAbove1 += (long long)h1[i];
                long long r = k - cAbove1;   // items to take in bin T1

                long long c2 = 0, cAbove2 = 0;
                double s2above = 0.0;
                int T2 = -1;
                for (int i = NB2 - 1; i >= 0; i--) {
                    long long cn = c2 + (long long)g_h2c[i];
                    if (cn >= r) { T2 = i; cAbove2 = c2; break; }
                    s2above += (double)g_h2s[i];
                    c2 = cn;
                }
                double part = 0.0;
                if (T2 >= 0 && g_h2c[T2] > 0u) {
                    long long r2 = r - cAbove2;
                    if (r2 < 0) r2 = 0;
                    part = (double)g_h2s[T2] * ((double)r2 / (double)g_h2c[T2]);
                }
                nsum = g_above_sum + s2above + part;
            } else {
                // fine path: all candidates are in above_sum; take the rest
                // from the 1024 fine bins over [0,0.5)
                long long cand = 0;
                for (int i = 0; i < NB1; i++) cand += (long long)h1[i];
                long long r = k - cand;
                long long c2 = 0, cAbove2 = 0;
                double s2above = 0.0;
                int T2 = -1;
                for (int i = NFB - 1; i >= 0; i--) {
                    long long cn = c2 + (long long)g_fc[i];
                    if (cn >= r) { T2 = i; cAbove2 = c2; break; }
                    s2above += (double)g_fs[i];
                    c2 = cn;
                }
                double part = 0.0;
                if (T2 >= 0 && g_fc[T2] > 0u) {
                    long long r2 = r - cAbove2;
                    if (r2 < 0) r2 = 0;
                    part = (double)g_fs[T2] * ((double)r2 / (double)g_fc[T2]);
                }
                nsum = g_above_sum + s2above + part;
            }
        }

        double denom = (double)pos + (double)k + 1e-6;
        out[0] = (float)((g_pos_sum + nsum) / denom);
    }
    __syncthreads();

    if (tid < NB1) g_h1[tid] = 0u;
    for (int i = tid; i < NB2; i += blockDim.x) { g_h2c[i] = 0u; g_h2s[i] = 0.0f; }
    for (int i = tid; i < NFB; i += blockDim.x) { g_fc[i] = 0u; g_fs[i] = 0.0f; }
    if (tid == 0) {
        g_pos_cnt   = 0u;
        g_neg_cnt   = 0u;
        g_pos_sum   = 0.0;
        g_above_sum = 0.0;
    }
}

// ---------------------------------------------------------------------------
extern "C" void kernel_launch(void* const* d_in, const int* in_sizes, int n_in,
                              void* d_out, int out_size)
{
    const float* pred = (const float*)d_in[0];
    const float* gt   = (const float*)d_in[1];
    const float* mask = (const float*)d_in[2];
    float* out = (float*)d_out;
    const int n = in_sizes[0];

    const float4* pred4 = (const float4*)pred;
    const float4* gt4   = (const float4*)gt;
    const float4* mask4 = (const float4*)mask;

    int n4 = n >> 2;
    int grid = (n4 + BLK - 1) / BLK;
    if (grid > GRID_CAP) grid = GRID_CAP;
    if (grid < 1) grid = 1;

    int iters = (n4 + grid * BLK - 1) / (grid * BLK);
    long long cap = (long long)iters * BLK * 4 + 8;
    int use_scr = ((long long)grid * cap <= (long long)SCR_SZ) ? 1 : 0;

    k1_scan  <<<grid, BLK>>>(pred4, gt4, mask4, pred, gt, mask, n, (int)cap, use_scr);
    k2_refine<<<grid, BLK>>>(pred4, gt4, mask4, pred, gt, mask, n, (int)cap, use_scr);
    k3_finalize<<<1, 256>>>(out);
}

// round 6
// speedup vs baseline: 1.2539x; 1.2539x over previous
#include <cuda_runtime.h>

// ---------------------------------------------------------------------------
// MaskedBalancedBCELoss — 4-kernel pipeline.
//  K1 (one 157 MB streaming read, NO histogram): counts pos/valid in regs;
//     ballot-compacts tagged candidates into per-block scratch regions
//     (negatives with p>=0.5 stored as +p, positives stored as -p).
//  K2a: 16-bin histogram (bins 16..31 of p*32) of negative candidates, built
//     from the 25 MB scratch (L2-resident).
//  K2b: derives threshold bin T1; one pass over scratch accumulating
//     log-sums via mantissa-product + exponent counter (no per-element log):
//       positives -> pos_sum,  negatives in bins > T1 -> above_sum,
//       negatives in bin == T1 -> exact log + 64-sub-bin count/sum hist.
//     Cold fallback (T1 below bin 16 / no scratch): full re-read with a
//     1024-fine-bin histogram. Always correct.
//  K3: resolves crossing sub-bin (mean interpolation), writes scalar, resets
//     all globals (CUDA-graph-replay safe).
// ---------------------------------------------------------------------------

#define NB1 16             // bins 16..31 of (int)(p*32)
#define NB2 64
#define NFB 1024           // fine bins over [0,0.5) for the cold fallback
#define BLK 256
#define GRID_CAP 888
#define SCR_SZ (16u << 20) // 16M floats = 64 MB

__device__ __align__(16) float g_scr[SCR_SZ];
__device__ unsigned int g_cnt_blk[GRID_CAP];
__device__ unsigned int g_h1[NB1];
__device__ unsigned int g_h2c[NB2];
__device__ float        g_h2s[NB2];
__device__ unsigned int g_fc[NFB];
__device__ float        g_fs[NFB];
__device__ unsigned int g_pos_cnt;
__device__ unsigned int g_neg_cnt;
__device__ double       g_pos_sum;
__device__ double       g_above_sum;

// Cephes-style natural log, pure FMA/ALU (no MUFU). ~1-2 ulp on normals.
__device__ __forceinline__ float fast_log(float x) {
    int   i  = __float_as_int(x);
    int   e  = ((i >> 23) & 0xFF) - 127;
    float m  = __int_as_float((i & 0x007FFFFF) | 0x3F800000);
    if (m > 1.41421356f) { m *= 0.5f; e += 1; }
    float t  = m - 1.0f;
    float z  = t * t;
    float P  = 7.0376836292e-2f;
    P = P * t - 1.1514610310e-1f;
    P = P * t + 1.1676998740e-1f;
    P = P * t - 1.2420140846e-1f;
    P = P * t + 1.4249322787e-1f;
    P = P * t - 1.6668057665e-1f;
    P = P * t + 2.0000714765e-1f;
    P = P * t - 2.4999993993e-1f;
    P = P * t + 3.3333331174e-1f;
    float fe = (float)e;
    float y  = t * z * P;
    y += fe * -2.12194440e-4f;
    y -= 0.5f * z;
    float r  = t + y;
    r += fe * 0.693359375f;
    return r;
}
__device__ __forceinline__ float pos_loss_f(float p) { return fminf(-fast_log(p), 100.0f); }
__device__ __forceinline__ float neg_loss_f(float p) { return fminf(-fast_log(1.0f - p), 100.0f); }

// log-sum accumulator: product of mantissas kept in [1,2), exponent in int.
// Caller guarantees x >= 1e-37 (normal).
__device__ __forceinline__ void acc_log(float x, float& m, int& e) {
    m *= x;
    int i = __float_as_int(m);
    e += ((i >> 23) & 0xFF) - 127;
    m = __int_as_float((i & 0x807FFFFFu) | 0x3F800000u);
}
// Sum of -log(x_i) accumulated in (m, e):
__device__ __forceinline__ float finish_log(float m, int e) {
    return -(fast_log(m) + (float)e * 0.69314718056f);
}

// Threshold bin from {16-bin candidate hist, neg_total, pos}.
// Returns: 1000 if k==0; -1 if threshold below bin 16 (cold); else T1 in [16,31].
__device__ __forceinline__ int find_T1(const unsigned* h1, unsigned pos,
                                       long long negtot, long long& k_out) {
    long long k3p = 3LL * (long long)pos;
    long long k = (pos == 0u) ? 0LL : (negtot < k3p ? negtot : k3p);
    k_out = k;
    if (k == 0) return 1000;
    long long c = 0;
    for (int i = NB1 - 1; i >= 0; i--) {
        c += (long long)h1[i];
        if (c >= k) return i + 16;
    }
    return -1;
}

// ---------------------------------------------------------------------------
// K1: stream, classify, compact. No histogram.
// ---------------------------------------------------------------------------
__global__ void __launch_bounds__(BLK) k1_scan(
    const float4* __restrict__ pred4, const float4* __restrict__ gt4,
    const float4* __restrict__ mask4,
    const float* __restrict__ pred, const float* __restrict__ gt,
    const float* __restrict__ mask, int n, int cap, int use_scr)
{
    __shared__ unsigned int s_cnt;
    __shared__ unsigned int w_pc[BLK / 32], w_vc[BLK / 32];

    const int tid  = threadIdx.x;
    const int lane = tid & 31;
    const unsigned lt = (1u << lane) - 1u;

    if (tid == 0) s_cnt = 0u;
    __syncthreads();

    unsigned int posc = 0, valc = 0;
    const int n4   = n >> 2;
    const int step = gridDim.x * BLK;
    const long long rb = (long long)blockIdx.x * (long long)cap;

    // classify: returns candidacy (pos, or neg with p>=0.5); v = tagged value
    auto procE = [&](float p, float g, float mm, bool in, float& v) -> bool {
        bool valid = in && (mm > 0.5f);
        bool ispos = valid && (g > 0.5f);
        valc += valid ? 1u : 0u;
        posc += ispos ? 1u : 0u;
        v = ispos ? -p : p;
        return ispos || (valid && !(g > 0.5f) && p >= 0.5f);
    };

    int ibase = blockIdx.x * BLK;
    while (ibase + step + BLK <= n4) {
        int i0 = ibase + tid, i1 = i0 + step;
        float4 pa = __ldcs(&pred4[i0]), ga = __ldcs(&gt4[i0]), ma = __ldcs(&mask4[i0]);
        float4 pb = __ldcs(&pred4[i1]), gb = __ldcs(&gt4[i1]), mb = __ldcs(&mask4[i1]);
        float v0, v1, v2, v3, v4, v5, v6, v7;
        bool c0 = procE(pa.x, ga.x, ma.x, true, v0);
        bool c1 = procE(pa.y, ga.y, ma.y, true, v1);
        bool c2 = procE(pa.z, ga.z, ma.z, true, v2);
        bool c3 = procE(pa.w, ga.w, ma.w, true, v3);
        bool c4 = procE(pb.x, gb.x, mb.x, true, v4);
        bool c5 = procE(pb.y, gb.y, mb.y, true, v5);
        bool c6 = procE(pb.z, gb.z, mb.z, true, v6);
        bool c7 = procE(pb.w, gb.w, mb.w, true, v7);
        if (use_scr) {
            unsigned m0 = __ballot_sync(0xffffffffu, c0);
            unsigned m1 = __ballot_sync(0xffffffffu, c1);
            unsigned m2 = __ballot_sync(0xffffffffu, c2);
            unsigned m3 = __ballot_sync(0xffffffffu, c3);
            unsigned m4 = __ballot_sync(0xffffffffu, c4);
            unsigned m5 = __ballot_sync(0xffffffffu, c5);
            unsigned m6 = __ballot_sync(0xffffffffu, c6);
            unsigned m7 = __ballot_sync(0xffffffffu, c7);
            unsigned tot = __popc(m0) + __popc(m1) + __popc(m2) + __popc(m3)
                         + __popc(m4) + __popc(m5) + __popc(m6) + __popc(m7);
            unsigned base = 0;
            if (lane == 0 && tot) base = atomicAdd(&s_cnt, tot);
            base = __shfl_sync(0xffffffffu, base, 0);
            unsigned s = base;
            if (c0) g_scr[rb + s + __popc(m0 & lt)] = v0; s += __popc(m0);
            if (c1) g_scr[rb + s + __popc(m1 & lt)] = v1; s += __popc(m1);
            if (c2) g_scr[rb + s + __popc(m2 & lt)] = v2; s += __popc(m2);
            if (c3) g_scr[rb + s + __popc(m3 & lt)] = v3; s += __popc(m3);
            if (c4) g_scr[rb + s + __popc(m4 & lt)] = v4; s += __popc(m4);
            if (c5) g_scr[rb + s + __popc(m5 & lt)] = v5; s += __popc(m5);
            if (c6) g_scr[rb + s + __popc(m6 & lt)] = v6; s += __popc(m6);
            if (c7) g_scr[rb + s + __popc(m7 & lt)] = v7;
        }
        ibase += 2 * step;
    }
    for (; ibase < n4; ibase += step) {   // block-uniform trips
        int i = ibase + tid;
        bool in = i < n4;
        float4 pa = in ? __ldcs(&pred4[i]) : make_float4(0.f, 0.f, 0.f, 0.f);
        float4 ga = in ? __ldcs(&gt4[i])   : make_float4(1.f, 1.f, 1.f, 1.f);
        float4 ma = in ? __ldcs(&mask4[i]) : make_float4(0.f, 0.f, 0.f, 0.f);
        float v0, v1, v2, v3;
        bool c0 = procE(pa.x, ga.x, ma.x, in, v0);
        bool c1 = procE(pa.y, ga.y, ma.y, in, v1);
        bool c2 = procE(pa.z, ga.z, ma.z, in, v2);
        bool c3 = procE(pa.w, ga.w, ma.w, in, v3);
        if (use_scr) {
            unsigned m0 = __ballot_sync(0xffffffffu, c0);
            unsigned m1 = __ballot_sync(0xffffffffu, c1);
            unsigned m2 = __ballot_sync(0xffffffffu, c2);
            unsigned m3 = __ballot_sync(0xffffffffu, c3);
            unsigned tot = __popc(m0) + __popc(m1) + __popc(m2) + __popc(m3);
            unsigned base = 0;
            if (lane == 0 && tot) base = atomicAdd(&s_cnt, tot);
            base = __shfl_sync(0xffffffffu, base, 0);
            unsigned s = base;
            if (c0) g_scr[rb + s + __popc(m0 & lt)] = v0; s += __popc(m0);
            if (c1) g_scr[rb + s + __popc(m1 & lt)] = v1; s += __popc(m1);
            if (c2) g_scr[rb + s + __popc(m2 & lt)] = v2; s += __popc(m2);
            if (c3) g_scr[rb + s + __popc(m3 & lt)] = v3;
        }
    }
    // scalar tail (n % 4), block 0 only
    if (blockIdx.x == 0) {
        for (int i = (n4 << 2) + tid; i < n; i += BLK) {
            float p = pred[i], g = gt[i], mm = mask[i];
            bool valid = mm > 0.5f;
            bool ispos = valid && (g > 0.5f);
            if (valid) valc++;
            if (ispos) posc++;
            if (use_scr && (ispos || (valid && !ispos && p >= 0.5f))) {
                unsigned o = atomicAdd(&s_cnt, 1u);
                g_scr[rb + o] = ispos ? -p : p;
            }
        }
    }

#pragma unroll
    for (int o = 16; o > 0; o >>= 1) {
        posc += __shfl_down_sync(0xffffffffu, posc, o);
        valc += __shfl_down_sync(0xffffffffu, valc, o);
    }
    if (lane == 0) { w_pc[tid >> 5] = posc; w_vc[tid >> 5] = valc; }
    __syncthreads();

    if (tid == 0) {
        unsigned pc = 0, vc = 0;
#pragma unroll
        for (int w = 0; w < BLK / 32; w++) { pc += w_pc[w]; vc += w_vc[w]; }
        if (pc) atomicAdd(&g_pos_cnt, pc);
        if (vc - pc) atomicAdd(&g_neg_cnt, vc - pc);
        g_cnt_blk[blockIdx.x] = s_cnt;
    }
}

// ---------------------------------------------------------------------------
// K2a: 16-bin candidate histogram from scratch (L2-resident)
// ---------------------------------------------------------------------------
__global__ void __launch_bounds__(BLK) k2a_hist(int cap, int use_scr)
{
    if (!use_scr) return;
    __shared__ unsigned int sh[4 * BLK];
    __shared__ unsigned int s_binsum[NB1];
    const int tid = threadIdx.x;
#pragma unroll
    for (int w = 0; w < 4; w++) sh[w * BLK + tid] = 0u;
    if (tid < NB1) s_binsum[tid] = 0u;
    __syncthreads();

    const long long rb = (long long)blockIdx.x * (long long)cap;
    const unsigned cnt = g_cnt_blk[blockIdx.x];
    auto hv = [&](float v) {
        if (v > 0.0f) {                       // negative candidate
            int idx = min((int)(v * 32.0f), 31) - 16;
            idx = max(idx, 0);
            sh[(idx >> 2) * BLK + tid] += 1u << ((idx & 3) << 3);
        }
    };
    const float4* s4 = (const float4*)&g_scr[rb];
    const unsigned c4 = cnt >> 2;
    for (unsigned j = tid; j < c4; j += BLK) {
        float4 v = s4[j];
        hv(v.x); hv(v.y); hv(v.z); hv(v.w);
    }
    for (unsigned j = (c4 << 2) + tid; j < cnt; j += BLK) hv(g_scr[rb + j]);
    __syncthreads();

    {   // staggered conflict-free flush
        const int b     = tid & 15;
        const int chunk = tid >> 4;
        const int w     = (b >> 2) * BLK;
        const int shft  = (b & 3) << 3;
        unsigned s = 0;
#pragma unroll
        for (int jj = 0; jj < 16; jj++) {
            int j = chunk * 16 + ((jj + b) & 15);
            s += (sh[w + j] >> shft) & 0xFFu;
        }
        if (s) atomicAdd(&s_binsum[b], s);
    }
    __syncthreads();
    if (tid < NB1 && s_binsum[tid]) atomicAdd(&g_h1[tid], s_binsum[tid]);
}

// ---------------------------------------------------------------------------
// K2b: log-product sums + bin-T1 sub-histogram
// ---------------------------------------------------------------------------
__global__ void __launch_bounds__(BLK) k2b_sums(
    const float4* __restrict__ pred4, const float4* __restrict__ gt4,
    const float4* __restrict__ mask4,
    const float* __restrict__ pred, const float* __restrict__ gt,
    const float* __restrict__ mask, int n, int cap, int use_scr)
{
    __shared__ unsigned int s_h1[NB1];
    __shared__ int          s_T1;
    __shared__ unsigned int s_c2[NB2];
    __shared__ float        s_s2[NB2];
    __shared__ unsigned int s_fc[NFB];
    __shared__ float        s_fs[NFB];
    __shared__ float        w_as[BLK / 32], w_ps[BLK / 32];

    const int tid = threadIdx.x;
    if (tid < NB1) s_h1[tid] = g_h1[tid];
    if (tid < NB2) { s_c2[tid] = 0u; s_s2[tid] = 0.0f; }
    for (int i = tid; i < NFB; i += BLK) { s_fc[i] = 0u; s_fs[i] = 0.0f; }
    __syncthreads();

    if (tid == 0) {
        long long k;
        s_T1 = find_T1(s_h1, g_pos_cnt, (long long)g_neg_cnt, k);
    }
    __syncthreads();
    const int T1 = s_T1;

    float mN = 1.0f, mP = 1.0f;     // mantissa products
    int   eN = 0,    eP = 0;        // exponent accumulators
    float asum = 0.0f, psum = 0.0f; // exact-path extras
    bool wrote_fine = false;

    if (use_scr && T1 >= 16 && T1 < 32) {
        const long long rb  = (long long)blockIdx.x * (long long)cap;
        const unsigned  cnt = g_cnt_blk[blockIdx.x];
        auto hv = [&](float v) {
            if (v < 0.0f) {                      // positive: loss = -log(p)
                float x = -v;
                if (x < 1e-37f) psum += fminf(-__logf(x), 100.0f);
                else            acc_log(x, mP, eP);
            } else {
                int b = min((int)(v * 32.0f), 31);
                if (b > T1) {                    // loss = -log(1-p)
                    float x = 1.0f - v;
                    if (x < 1e-37f) asum += fminf(-__logf(x), 100.0f);
                    else            acc_log(x, mN, eN);
                } else if (b == T1) {
                    int b2 = (int)(v * 2048.0f) - T1 * 64;
                    b2 = max(0, min(b2, NB2 - 1));
                    atomicAdd(&s_c2[b2], 1u);
                    atomicAdd(&s_s2[b2], neg_loss_f(v));
                }
            }
        };
        const float4* s4 = (const float4*)&g_scr[rb];
        const unsigned c4 = cnt >> 2;
        for (unsigned j = tid; j < c4; j += BLK) {
            float4 v = s4[j];
            hv(v.x); hv(v.y); hv(v.z); hv(v.w);
        }
        for (unsigned j = (c4 << 2) + tid; j < cnt; j += BLK) hv(g_scr[rb + j]);
    } else if (use_scr && T1 == 1000) {
        // k == 0: only positive losses
        const long long rb  = (long long)blockIdx.x * (long long)cap;
        const unsigned  cnt = g_cnt_blk[blockIdx.x];
        for (unsigned j = tid; j < cnt; j += BLK) {
            float v = g_scr[rb + j];
            if (v < 0.0f) {
                float x = -v;
                if (x < 1e-37f) psum += fminf(-__logf(x), 100.0f);
                else            acc_log(x, mP, eP);
            }
        }
    } else {
        // cold path: full re-read
        const bool fine = (T1 >= 0 && T1 < 16) || T1 == -1;
        wrote_fine = (T1 != 1000);
        const int n4 = n >> 2;
        const int stp = gridDim.x * BLK;
        auto hfull = [&](float p, float g, float mm) {
            if (mm > 0.5f) {
                if (g > 0.5f) { psum += pos_loss_f(p); return; }
                if (T1 == 1000) return;
                if (fine) {
                    if (p >= 0.5f) asum += neg_loss_f(p);
                    else {
                        int fb = max(0, min((int)(p * 2048.0f), NFB - 1));
                        atomicAdd(&s_fc[fb], 1u);
                        atomicAdd(&s_fs[fb], neg_loss_f(p));
                    }
                }
            }
        };
        for (int ib = blockIdx.x * BLK; ib < n4; ib += stp) {
            int i = ib + tid;
            if (i < n4) {
                float4 p = pred4[i], g = gt4[i], m = mask4[i];
                hfull(p.x, g.x, m.x); hfull(p.y, g.y, m.y);
                hfull(p.z, g.z, m.z); hfull(p.w, g.w, m.w);
            }
        }
        if (blockIdx.x == 0) {
            for (int i = (n4 << 2) + tid; i < n; i += BLK)
                hfull(pred[i], gt[i], mask[i]);
        }
    }

    asum += finish_log(mN, eN);
    psum += finish_log(mP, eP);

#pragma unroll
    for (int o = 16; o > 0; o >>= 1) {
        asum += __shfl_down_sync(0xffffffffu, asum, o);
        psum += __shfl_down_sync(0xffffffffu, psum, o);
    }
    if ((tid & 31) == 0) { w_as[tid >> 5] = asum; w_ps[tid >> 5] = psum; }
    __syncthreads();

    if (tid < NB2 && s_c2[tid]) {
        atomicAdd(&g_h2c[tid], s_c2[tid]);
        atomicAdd(&g_h2s[tid], s_s2[tid]);
    }
    if (wrote_fine) {
        for (int i = tid; i < NFB; i += BLK) {
            if (s_fc[i]) { atomicAdd(&g_fc[i], s_fc[i]); atomicAdd(&g_fs[i], s_fs[i]); }
        }
    }
    if (tid == 0) {
        float as = 0.0f, ps = 0.0f;
#pragma unroll
        for (int w = 0; w < BLK / 32; w++) { as += w_as[w]; ps += w_ps[w]; }
        atomicAdd(&g_above_sum, (double)as);
        atomicAdd(&g_pos_sum, (double)ps);
    }
}

// ---------------------------------------------------------------------------
// K3: finalize + reset globals
// ---------------------------------------------------------------------------
__global__ void k3_finalize(float* __restrict__ out, int use_scr)
{
    const int tid = threadIdx.x;
    if (tid == 0) {
        unsigned pos = g_pos_cnt;
        long long k;
        unsigned h1[NB1];
        for (int i = 0; i < NB1; i++) h1[i] = g_h1[i];
        int T1 = use_scr ? find_T1(h1, pos, (long long)g_neg_cnt, k) : -1;
        if (!use_scr) {   // cold: recompute k
            long long k3p = 3LL * (long long)pos;
            long long nt = (long long)g_neg_cnt;
            k = (pos == 0u) ? 0LL : (nt < k3p ? nt : k3p);
            if (k == 0) T1 = 1000;
        }

        double nsum = 0.0;
        if (k > 0) {
            if (T1 >= 16 && T1 < 32) {
                long long cAbove1 = 0;
                for (int i = T1 + 1 - 16; i < NB1; i++) cAbove1 += (long long)h1[i];
                long long r = k - cAbove1;   // items to take in bin T1

                long long c2 = 0, cAbove2 = 0;
                double s2above = 0.0;
                int T2 = -1;
                for (int i = NB2 - 1; i >= 0; i--) {
                    long long cn = c2 + (long long)g_h2c[i];
                    if (cn >= r) { T2 = i; cAbove2 = c2; break; }
                    s2above += (double)g_h2s[i];
                    c2 = cn;
                }
                double part = 0.0;
                if (T2 >= 0 && g_h2c[T2] > 0u) {
                    long long r2 = r - cAbove2;
                    if (r2 < 0) r2 = 0;
                    part = (double)g_h2s[T2] * ((double)r2 / (double)g_h2c[T2]);
                }
                nsum = g_above_sum + s2above + part;
            } else {
                // fine path: above_sum covers p>=0.5; take the rest from the
                // 1024 fine bins over [0,0.5)
                long long cUpper = 0;
                // count of negatives with p>=0.5 = neg_total - sum(fine bins)
                long long fineTot = 0;
                for (int i = 0; i < NFB; i++) fineTot += (long long)g_fc[i];
                cUpper = (long long)g_neg_cnt - fineTot;
                long long r = k - cUpper;
                long long c2 = 0, cAbove2 = 0;
                double s2above = 0.0;
                int T2 = -1;
                for (int i = NFB - 1; i >= 0; i--) {
                    long long cn = c2 + (long long)g_fc[i];
                    if (cn >= r) { T2 = i; cAbove2 = c2; break; }
                    s2above += (double)g_fs[i];
                    c2 = cn;
                }
                double part = 0.0;
                if (T2 >= 0 && g_fc[T2] > 0u) {
                    long long r2 = r - cAbove2;
                    if (r2 < 0) r2 = 0;
                    part = (double)g_fs[T2] * ((double)r2 / (double)g_fc[T2]);
                }
                nsum = g_above_sum + s2above + part;
            }
        }

        double denom = (double)pos + (double)k + 1e-6;
        out[0] = (float)((g_pos_sum + nsum) / denom);
    }
    __syncthreads();

    if (tid < NB1) g_h1[tid] = 0u;
    for (int i = tid; i < NB2; i += blockDim.x) { g_h2c[i] = 0u; g_h2s[i] = 0.0f; }
    for (int i = tid; i < NFB; i += blockDim.x) { g_fc[i] = 0u; g_fs[i] = 0.0f; }
    if (tid == 0) {
        g_pos_cnt   = 0u;
        g_neg_cnt   = 0u;
        g_pos_sum   = 0.0;
        g_above_sum = 0.0;
    }
}

// ---------------------------------------------------------------------------
extern "C" void kernel_launch(void* const* d_in, const int* in_sizes, int n_in,
                              void* d_out, int out_size)
{
    const float* pred = (const float*)d_in[0];
    const float* gt   = (const float*)d_in[1];
    const float* mask = (const float*)d_in[2];
    float* out = (float*)d_out;
    const int n = in_sizes[0];

    const float4* pred4 = (const float4*)pred;
    const float4* gt4   = (const float4*)gt;
    const float4* mask4 = (const float4*)mask;

    int n4 = n >> 2;
    int grid = (n4 + BLK - 1) / BLK;
    if (grid > GRID_CAP) grid = GRID_CAP;
    if (grid < 1) grid = 1;

    int iters = (n4 + grid * BLK - 1) / (grid * BLK);
    long long cap = (long long)iters * BLK * 4 + 8;
    int use_scr = ((long long)grid * cap <= (long long)SCR_SZ) ? 1 : 0;

    k1_scan <<<grid, BLK>>>(pred4, gt4, mask4, pred, gt, mask, n, (int)cap, use_scr);
    k2a_hist<<<grid, BLK>>>((int)cap, use_scr);
    k2b_sums<<<grid, BLK>>>(pred4, gt4, mask4, pred, gt, mask, n, (int)cap, use_scr);
    k3_finalize<<<1, 256>>>(out, use_scr);
}